// round 6
// baseline (speedup 1.0000x reference)
#include <cuda_runtime.h>
#include <cuda_bf16.h>
#include <cstdint>
#include <cstddef>

// ---------------- problem dims ----------------
#define LDIM 2048
#define BDIM 32
#define DDIM 1024
#define MDIM (LDIM*BDIM)     // 65536 rows (l*32+b)
#define KDIM DDIM            // 1024
#define NDIM (3*DDIM)        // 3072

// ---------------- scratch (device globals; allocation-free rule) ----------------
__device__ float g_xr[(size_t)MDIM * KDIM];   // tf32-rounded x        (268 MB)
__device__ float g_wT[(size_t)NDIM * KDIM];   // W^T, tf32-rounded     (12.6 MB)
__device__ float g_u [(size_t)MDIM * NDIM];   // u = x @ W             (805 MB)

// ---------------- helpers ----------------
__device__ __forceinline__ uint32_t smem_u32(const void* p) {
    uint32_t a;
    asm("{ .reg .u64 t; cvta.to.shared.u64 t, %1; cvt.u32.u64 %0, t; }" : "=r"(a) : "l"(p));
    return a;
}
__device__ __forceinline__ float tf32r(float a) {
    uint32_t o; asm("cvt.rna.tf32.f32 %0, %1;" : "=r"(o) : "f"(a));
    return __uint_as_float(o);
}
__device__ __forceinline__ void cp16(uint32_t s, const void* g) {
    asm volatile("cp.async.cg.shared.global [%0], [%1], 16;" :: "r"(s), "l"(g));
}
__device__ __forceinline__ float sigmoidf_fast(float z) {
    float e = __expf(-z);
    return __fdividef(1.0f, 1.0f + e);
}

// ---------------- GEMM config ----------------
#define GBM 256
#define GBN 128
#define GBK 32
#define GTHREADS 512
#define GSTAGES 3
#define NTILES (NDIM / GBN)              // 24
#define NCHUNK (KDIM / GBK)              // 32
#define A_FLOATS (GBM * GBK)             // 8192
#define B_FLOATS (GBN * GBK)             // 4096
#define STAGE_FLOATS (A_FLOATS + B_FLOATS)   // 12288 floats = 48 KB
#define GSMEM_BYTES (GSTAGES * STAGE_FLOATS * 4)  // 147456

// swizzled float index inside a tile with 32-float rows, 16B-block XOR swizzle
__device__ __forceinline__ int saddr(int row, int col) {
    return row * 32 + ((((col >> 2) ^ (row & 7)) << 2) | (col & 3));
}

// ---------------- pre-passes ----------------
__global__ void xround_kernel(const float4* __restrict__ x) {
    size_t i = (size_t)blockIdx.x * blockDim.x + threadIdx.x;   // 16,777,216 float4s
    float4 v = x[i];
    v.x = tf32r(v.x); v.y = tf32r(v.y); v.z = tf32r(v.z); v.w = tf32r(v.w);
    reinterpret_cast<float4*>(g_xr)[i] = v;
}

__global__ void wtrans_kernel(const float* __restrict__ w) {
    __shared__ float tile[32][33];
    int n0 = blockIdx.x * 32, k0 = blockIdx.y * 32;
    int tx = threadIdx.x, ty = threadIdx.y;   // block (32, 8)
#pragma unroll
    for (int i = 0; i < 32; i += 8)
        tile[ty + i][tx] = w[(size_t)(k0 + ty + i) * NDIM + n0 + tx];
    __syncthreads();
#pragma unroll
    for (int i = 0; i < 32; i += 8)
        g_wT[(size_t)(n0 + ty + i) * KDIM + k0 + tx] = tf32r(tile[tx][ty + i]);
}

// ---------------- tf32 mma.sync GEMM ----------------
// u[m][n] = sum_k xr[m][k] * wT[n][k]  (A row-major, B col-major == wT[N][K] row-major)
__device__ __forceinline__ void load_stage(uint32_t sbytes, int mt, int nt, int kc, int tid) {
    // A: 2048 float4s, 4 per thread
    const float* aG = g_xr + ((size_t)mt * GBM) * KDIM + (size_t)kc * GBK;
#pragma unroll
    for (int i = 0; i < 4; i++) {
        int g = tid + i * GTHREADS;
        int row = g >> 3, f4c = g & 7;
        uint32_t dst = sbytes + (uint32_t)(row * 32 + ((f4c ^ (row & 7)) << 2)) * 4;
        cp16(dst, aG + (size_t)row * KDIM + f4c * 4);
    }
    // B: 1024 float4s, 2 per thread
    const float* bG = g_wT + ((size_t)nt * GBN) * KDIM + (size_t)kc * GBK;
#pragma unroll
    for (int i = 0; i < 2; i++) {
        int g = tid + i * GTHREADS;
        int row = g >> 3, f4c = g & 7;
        uint32_t dst = sbytes + (uint32_t)(A_FLOATS + row * 32 + ((f4c ^ (row & 7)) << 2)) * 4;
        cp16(dst, bG + (size_t)row * KDIM + f4c * 4);
    }
    asm volatile("cp.async.commit_group;" ::: "memory");
}

__global__ void __launch_bounds__(GTHREADS, 1) gemm_tf32_kernel() {
    extern __shared__ float smem[];
    uint32_t sbytes = smem_u32(smem);
    int tid = threadIdx.x;
    int mt = blockIdx.x / NTILES;
    int nt = blockIdx.x % NTILES;

    int wid = tid >> 5, lane = tid & 31;
    int wm = wid & 3, wn = wid >> 2;          // 4 x 4 warp grid
    int gid = lane >> 2, tg = lane & 3;

    float acc[4][4][4];                       // [mi][ni][c0..c3]
#pragma unroll
    for (int a = 0; a < 4; a++)
#pragma unroll
        for (int b = 0; b < 4; b++)
#pragma unroll
            for (int c = 0; c < 4; c++) acc[a][b][c] = 0.0f;

    // prologue: 2 stages in flight
    load_stage(sbytes, mt, nt, 0, tid);
    load_stage(sbytes + STAGE_FLOATS * 4, mt, nt, 1, tid);

    for (int c = 0; c < NCHUNK; c++) {
        if (c == NCHUNK - 1) asm volatile("cp.async.wait_group 0;" ::: "memory");
        else                 asm volatile("cp.async.wait_group 1;" ::: "memory");
        __syncthreads();

        if (c + 2 < NCHUNK)
            load_stage(sbytes + ((c + 2) % GSTAGES) * STAGE_FLOATS * 4, mt, nt, c + 2, tid);

        const float* sA = smem + (c % GSTAGES) * STAGE_FLOATS;
        const float* sB = sA + A_FLOATS;

#pragma unroll
        for (int ks = 0; ks < 4; ks++) {
            uint32_t af[4][4], bf[4][2];
            int kc0 = ks * 8 + tg;
#pragma unroll
            for (int mi = 0; mi < 4; mi++) {
                int r0 = wm * 64 + mi * 16 + gid;
                af[mi][0] = __float_as_uint(sA[saddr(r0,     kc0)]);
                af[mi][1] = __float_as_uint(sA[saddr(r0 + 8, kc0)]);
                af[mi][2] = __float_as_uint(sA[saddr(r0,     kc0 + 4)]);
                af[mi][3] = __float_as_uint(sA[saddr(r0 + 8, kc0 + 4)]);
            }
#pragma unroll
            for (int ni = 0; ni < 4; ni++) {
                int n0 = wn * 32 + ni * 8 + gid;
                bf[ni][0] = __float_as_uint(sB[saddr(n0, kc0)]);
                bf[ni][1] = __float_as_uint(sB[saddr(n0, kc0 + 4)]);
            }
#pragma unroll
            for (int mi = 0; mi < 4; mi++)
#pragma unroll
                for (int ni = 0; ni < 4; ni++) {
                    asm volatile(
                        "mma.sync.aligned.m16n8k8.row.col.f32.tf32.tf32.f32 "
                        "{%0,%1,%2,%3}, {%4,%5,%6,%7}, {%8,%9}, {%0,%1,%2,%3};"
                        : "+f"(acc[mi][ni][0]), "+f"(acc[mi][ni][1]),
                          "+f"(acc[mi][ni][2]), "+f"(acc[mi][ni][3])
                        : "r"(af[mi][0]), "r"(af[mi][1]), "r"(af[mi][2]), "r"(af[mi][3]),
                          "r"(bf[ni][0]), "r"(bf[ni][1]));
                }
        }
        __syncthreads();
    }

    // epilogue: float2 stores (c0,c1 contiguous)
#pragma unroll
    for (int mi = 0; mi < 4; mi++) {
#pragma unroll
        for (int ni = 0; ni < 4; ni++) {
            int row = mt * GBM + wm * 64 + mi * 16 + gid;
            int col = nt * GBN + wn * 32 + ni * 8 + tg * 2;
            float2 v0 = make_float2(acc[mi][ni][0], acc[mi][ni][1]);
            float2 v1 = make_float2(acc[mi][ni][2], acc[mi][ni][3]);
            *reinterpret_cast<float2*>(g_u + (size_t)row * NDIM + col) = v0;
            *reinterpret_cast<float2*>(g_u + (size_t)(row + 8) * NDIM + col) = v1;
        }
    }
}

// ---------------- sequential scan ----------------
// one thread per (b, d) lane; depth-4 register prefetch ring
__global__ void __launch_bounds__(256) scan_kernel(
    const float* __restrict__ x, const float* __restrict__ wc,
    const float* __restrict__ bias, const float* __restrict__ sxp,
    float* __restrict__ out) {
    int t = blockIdx.x * 256 + threadIdx.x;    // 0..32767
    int d = t & (DDIM - 1), b = t >> 10;
    float fw = wc[d], rw = wc[DDIM + d];
    float fb = bias[d], rb = bias[DDIM + d];
    float sx = sxp[0];

    const float* up = g_u + (size_t)b * NDIM + 3 * d;   // + l*32*NDIM per step
    const float* xq = x + (size_t)b * DDIM + d;         // + l*32*DDIM per step
    float* hp = out + (size_t)b * DDIM + d;

    float4 buf[4];
#pragma unroll
    for (int j = 0; j < 4; j++) {
        size_t ru = (size_t)j * BDIM * NDIM;
        buf[j].x = __ldg(up + ru);
        buf[j].y = __ldg(up + ru + 1);
        buf[j].z = __ldg(up + ru + 2);
        buf[j].w = __ldg(xq + (size_t)j * BDIM * DDIM);
    }

    float c = 0.0f;
    for (int l = 0; l < LDIM; l += 4) {
#pragma unroll
        for (int j = 0; j < 4; j++) {
            float u0 = buf[j].x;
            float u1 = buf[j].y + fb;
            float u2 = buf[j].z + rb;
            float xv = buf[j].w * sx;
            int ln = l + j + 4;
            if (ln < LDIM) {                    // prefetch step ln
                size_t ru = (size_t)ln * BDIM * NDIM;
                buf[j].x = __ldg(up + ru);
                buf[j].y = __ldg(up + ru + 1);
                buf[j].z = __ldg(up + ru + 2);
                buf[j].w = __ldg(xq + (size_t)ln * BDIM * DDIM);
            }
            float f = sigmoidf_fast(fmaf(c, fw, u1));
            float r = sigmoidf_fast(fmaf(c, rw, u2));
            c = fmaf(c - u0, f, u0);            // u0 + (c-u0)*f
            float h = fmaf(c - xv, r, xv);      // xp + (c-xp)*r
            hp[(size_t)(l + j) * BDIM * DDIM] = h;
        }
    }
    out[(size_t)LDIM * BDIM * DDIM + (size_t)b * DDIM + d] = c;   // c_final
}

// ---------------- launch ----------------
extern "C" void kernel_launch(void* const* d_in, const int* in_sizes, int n_in,
                              void* d_out, int out_size) {
    const float* x    = (const float*)d_in[0];
    const float* w    = (const float*)d_in[1];
    const float* wc   = (const float*)d_in[2];
    const float* bias = (const float*)d_in[3];
    const float* sx   = (const float*)d_in[4];
    float* out = (float*)d_out;

    cudaFuncSetAttribute(gemm_tf32_kernel,
                         cudaFuncAttributeMaxDynamicSharedMemorySize, GSMEM_BYTES);

    xround_kernel<<<MDIM * KDIM / 4 / 256, 256>>>((const float4*)x);
    wtrans_kernel<<<dim3(NDIM / 32, KDIM / 32), dim3(32, 8)>>>(w);
    gemm_tf32_kernel<<<(MDIM / GBM) * NTILES, GTHREADS, GSMEM_BYTES>>>();
    scan_kernel<<<BDIM * DDIM / 256, 256>>>(x, wc, bias, sx, out);
}

// round 13
// speedup vs baseline: 1.1263x; 1.1263x over previous
#include <cuda_runtime.h>
#include <cuda_bf16.h>
#include <cstdint>
#include <cstddef>

// ---------------- problem dims ----------------
#define LDIM 2048
#define BDIM 32
#define DDIM 1024
#define MDIM (LDIM*BDIM)     // 65536 rows (l*32+b)
#define KDIM DDIM            // 1024
#define NDIM (3*DDIM)        // 3072

// ---------------- scratch (device globals; allocation-free rule) ----------------
__device__ float g_xr[(size_t)MDIM * KDIM];   // tf32-rounded x        (268 MB)
__device__ float g_wT[(size_t)NDIM * KDIM];   // W^T, tf32-rounded     (12.6 MB)
__device__ float g_u [(size_t)MDIM * NDIM];   // u = x @ W             (805 MB)

// ---------------- helpers ----------------
__device__ __forceinline__ uint32_t smem_u32(const void* p) {
    uint32_t a;
    asm("{ .reg .u64 t; cvta.to.shared.u64 t, %1; cvt.u32.u64 %0, t; }" : "=r"(a) : "l"(p));
    return a;
}
__device__ __forceinline__ float tf32r(float a) {
    uint32_t o; asm("cvt.rna.tf32.f32 %0, %1;" : "=r"(o) : "f"(a));
    return __uint_as_float(o);
}
__device__ __forceinline__ void cp16(uint32_t s, const void* g) {
    asm volatile("cp.async.cg.shared.global [%0], [%1], 16;" :: "r"(s), "l"(g));
}
__device__ __forceinline__ float sigmoidf_fast(float z) {
    float e = __expf(-z);
    return __fdividef(1.0f, 1.0f + e);
}

// ---------------- GEMM config ----------------
#define GBM 256
#define GBN 128
#define GBK 32
#define GTHREADS 512
#define GSTAGES 3
#define NTILES (NDIM / GBN)              // 24
#define NCHUNK (KDIM / GBK)              // 32
#define A_FLOATS (GBM * GBK)             // 8192
#define B_FLOATS (GBN * GBK)             // 4096
#define STAGE_FLOATS (A_FLOATS + B_FLOATS)   // 12288 floats = 48 KB
#define GSMEM_BYTES (GSTAGES * STAGE_FLOATS * 4)  // 147456

// ---------------- pre-passes ----------------
__global__ void xround_kernel(const float4* __restrict__ x) {
    size_t i = (size_t)blockIdx.x * blockDim.x + threadIdx.x;   // 16,777,216 float4s
    float4 v = x[i];
    v.x = tf32r(v.x); v.y = tf32r(v.y); v.z = tf32r(v.z); v.w = tf32r(v.w);
    reinterpret_cast<float4*>(g_xr)[i] = v;
}

__global__ void wtrans_kernel(const float* __restrict__ w) {
    __shared__ float tile[32][33];
    int n0 = blockIdx.x * 32, k0 = blockIdx.y * 32;
    int tx = threadIdx.x, ty = threadIdx.y;   // block (32, 8)
#pragma unroll
    for (int i = 0; i < 32; i += 8)
        tile[ty + i][tx] = w[(size_t)(k0 + ty + i) * NDIM + n0 + tx];
    __syncthreads();
#pragma unroll
    for (int i = 0; i < 32; i += 8)
        g_wT[(size_t)(n0 + ty + i) * KDIM + k0 + tx] = tf32r(tile[tx][ty + i]);
}

// ---------------- tf32 mma.sync GEMM ----------------
// u[m][n] = sum_k xr[m][k] * wT[n][k]  (A row-major, B col-major == wT[N][K] row-major)
// SMEM tile layout: row-major 32 floats/row, 16B-granule XOR swizzle:
//   granule f4c of row stored at granule (f4c ^ (row&7)).
__device__ __forceinline__ void load_stage(uint32_t sbytes, int mt, int nt, int kc, int tid) {
    // A: 2048 float4s, 4 per thread
    const float* aG = g_xr + ((size_t)mt * GBM) * KDIM + (size_t)kc * GBK;
#pragma unroll
    for (int i = 0; i < 4; i++) {
        int g = tid + i * GTHREADS;
        int row = g >> 3, f4c = g & 7;
        uint32_t dst = sbytes + (uint32_t)(row * 32 + ((f4c ^ (row & 7)) << 2)) * 4;
        cp16(dst, aG + (size_t)row * KDIM + f4c * 4);
    }
    // B: 1024 float4s, 2 per thread
    const float* bG = g_wT + ((size_t)nt * GBN) * KDIM + (size_t)kc * GBK;
#pragma unroll
    for (int i = 0; i < 2; i++) {
        int g = tid + i * GTHREADS;
        int row = g >> 3, f4c = g & 7;
        uint32_t dst = sbytes + (uint32_t)(A_FLOATS + row * 32 + ((f4c ^ (row & 7)) << 2)) * 4;
        cp16(dst, bG + (size_t)row * KDIM + f4c * 4);
    }
    asm volatile("cp.async.commit_group;" ::: "memory");
}

// tf32 mma with float-typed operands (bit-passed as .b32)
#define MMA_TF32(ACC, A0, A1, A2, A3, B0, B1)                                   \
    asm volatile(                                                               \
        "mma.sync.aligned.m16n8k8.row.col.f32.tf32.tf32.f32 "                   \
        "{%0,%1,%2,%3}, {%4,%5,%6,%7}, {%8,%9}, {%0,%1,%2,%3};"                 \
        : "+f"((ACC)[0]), "+f"((ACC)[1]), "+f"((ACC)[2]), "+f"((ACC)[3])        \
        : "r"(__float_as_uint(A0)), "r"(__float_as_uint(A1)),                   \
          "r"(__float_as_uint(A2)), "r"(__float_as_uint(A3)),                   \
          "r"(__float_as_uint(B0)), "r"(__float_as_uint(B1)))

__global__ void __launch_bounds__(GTHREADS, 1) gemm_tf32_kernel() {
    extern __shared__ float smem[];
    uint32_t sbytes = smem_u32(smem);
    int tid = threadIdx.x;
    int mt = blockIdx.x / NTILES;
    int nt = blockIdx.x % NTILES;

    int wid = tid >> 5, lane = tid & 31;
    int wm = wid & 3, wn = wid >> 2;          // 4 x 4 warp grid
    int gid = lane >> 2, tg = lane & 3;

    float acc[4][4][4];                       // [mi][ni][c0..c3]
#pragma unroll
    for (int a = 0; a < 4; a++)
#pragma unroll
        for (int b = 0; b < 4; b++)
#pragma unroll
            for (int c = 0; c < 4; c++) acc[a][b][c] = 0.0f;

    // prologue: 2 stages in flight
    load_stage(sbytes, mt, nt, 0, tid);
    load_stage(sbytes + STAGE_FLOATS * 4, mt, nt, 1, tid);

    for (int c = 0; c < NCHUNK; c++) {
        if (c == NCHUNK - 1) asm volatile("cp.async.wait_group 0;" ::: "memory");
        else                 asm volatile("cp.async.wait_group 1;" ::: "memory");
        __syncthreads();

        if (c + 2 < NCHUNK)
            load_stage(sbytes + ((c + 2) % GSTAGES) * STAGE_FLOATS * 4, mt, nt, c + 2, tid);

        const float* sA = smem + (c % GSTAGES) * STAGE_FLOATS;
        const float* sB = sA + A_FLOATS;

        // K-permuted fragment scheme: granule g = tg + 4h holds global cols
        // 16h+4tg .. 16h+4tg+3. mma (h,j) maps fragment position tg -> col
        // 16h+4tg+j and position tg+4 -> col 16h+4tg+j+2 (j in {0,1}).
        // Same map for A and B => product invariant under k-permutation.
#pragma unroll
        for (int h = 0; h < 2; h++) {
            int g = tg + 4 * h;
            float4 aLo[4], aHi[4], bV[4];
#pragma unroll
            for (int mi = 0; mi < 4; mi++) {
                int rLo = wm * 64 + mi * 16 + gid;      // &7 == gid
                int rHi = rLo + 8;                      // &7 == gid
                aLo[mi] = *reinterpret_cast<const float4*>(
                    sA + rLo * 32 + ((g ^ gid) << 2));
                aHi[mi] = *reinterpret_cast<const float4*>(
                    sA + rHi * 32 + ((g ^ gid) << 2));
            }
#pragma unroll
            for (int ni = 0; ni < 4; ni++) {
                int rN = wn * 32 + ni * 8 + gid;        // &7 == gid
                bV[ni] = *reinterpret_cast<const float4*>(
                    sB + rN * 32 + ((g ^ gid) << 2));
            }
#pragma unroll
            for (int j = 0; j < 2; j++) {
#pragma unroll
                for (int mi = 0; mi < 4; mi++) {
                    const float* al = reinterpret_cast<const float*>(&aLo[mi]);
                    const float* ah = reinterpret_cast<const float*>(&aHi[mi]);
#pragma unroll
                    for (int ni = 0; ni < 4; ni++) {
                        const float* bv = reinterpret_cast<const float*>(&bV[ni]);
                        MMA_TF32(acc[mi][ni],
                                 al[j], ah[j], al[j + 2], ah[j + 2],
                                 bv[j], bv[j + 2]);
                    }
                }
            }
        }
        __syncthreads();
    }

    // epilogue: float2 stores (c0,c1 contiguous)
#pragma unroll
    for (int mi = 0; mi < 4; mi++) {
#pragma unroll
        for (int ni = 0; ni < 4; ni++) {
            int row = mt * GBM + wm * 64 + mi * 16 + gid;
            int col = nt * GBN + wn * 32 + ni * 8 + tg * 2;
            float2 v0 = make_float2(acc[mi][ni][0], acc[mi][ni][1]);
            float2 v1 = make_float2(acc[mi][ni][2], acc[mi][ni][3]);
            *reinterpret_cast<float2*>(g_u + (size_t)row * NDIM + col) = v0;
            *reinterpret_cast<float2*>(g_u + (size_t)(row + 8) * NDIM + col) = v1;
        }
    }
}

// ---------------- sequential scan ----------------
// one thread per (b, d) lane; depth-8 register prefetch ring (32 loads in flight)
#define RING 8
__global__ void __launch_bounds__(256) scan_kernel(
    const float* __restrict__ x, const float* __restrict__ wc,
    const float* __restrict__ bias, const float* __restrict__ sxp,
    float* __restrict__ out) {
    int t = blockIdx.x * 256 + threadIdx.x;    // 0..32767
    int d = t & (DDIM - 1), b = t >> 10;
    float fw = wc[d], rw = wc[DDIM + d];
    float fb = bias[d], rb = bias[DDIM + d];
    float sx = sxp[0];

    const float* up = g_u + (size_t)b * NDIM + 3 * d;   // + l*32*NDIM per step
    const float* xq = x + (size_t)b * DDIM + d;         // + l*32*DDIM per step
    float* hp = out + (size_t)b * DDIM + d;

    float4 buf[RING];
#pragma unroll
    for (int j = 0; j < RING; j++) {
        size_t ru = (size_t)j * BDIM * NDIM;
        buf[j].x = __ldg(up + ru);
        buf[j].y = __ldg(up + ru + 1);
        buf[j].z = __ldg(up + ru + 2);
        buf[j].w = __ldg(xq + (size_t)j * BDIM * DDIM);
    }

    float c = 0.0f;
    for (int l = 0; l < LDIM; l += RING) {
#pragma unroll
        for (int j = 0; j < RING; j++) {
            float u0 = buf[j].x;
            float u1 = buf[j].y + fb;
            float u2 = buf[j].z + rb;
            float xv = buf[j].w * sx;
            int ln = l + j + RING;
            if (ln < LDIM) {                    // prefetch step ln
                size_t ru = (size_t)ln * BDIM * NDIM;
                buf[j].x = __ldg(up + ru);
                buf[j].y = __ldg(up + ru + 1);
                buf[j].z = __ldg(up + ru + 2);
                buf[j].w = __ldg(xq + (size_t)ln * BDIM * DDIM);
            }
            float f = sigmoidf_fast(fmaf(c, fw, u1));
            float r = sigmoidf_fast(fmaf(c, rw, u2));
            c = fmaf(c - u0, f, u0);            // u0 + (c-u0)*f
            float h = fmaf(c - xv, r, xv);      // xp + (c-xp)*r
            hp[(size_t)(l + j) * BDIM * DDIM] = h;
        }
    }
    out[(size_t)LDIM * BDIM * DDIM + (size_t)b * DDIM + d] = c;   // c_final
}

// ---------------- launch ----------------
extern "C" void kernel_launch(void* const* d_in, const int* in_sizes, int n_in,
                              void* d_out, int out_size) {
    const float* x    = (const float*)d_in[0];
    const float* w    = (const float*)d_in[1];
    const float* wc   = (const float*)d_in[2];
    const float* bias = (const float*)d_in[3];
    const float* sx   = (const float*)d_in[4];
    float* out = (float*)d_out;

    cudaFuncSetAttribute(gemm_tf32_kernel,
                         cudaFuncAttributeMaxDynamicSharedMemorySize, GSMEM_BYTES);

    xround_kernel<<<MDIM * KDIM / 4 / 256, 256>>>((const float4*)x);
    wtrans_kernel<<<dim3(NDIM / 32, KDIM / 32), dim3(32, 8)>>>(w);
    gemm_tf32_kernel<<<(MDIM / GBM) * NTILES, GTHREADS, GSMEM_BYTES>>>();
    scan_kernel<<<BDIM * DDIM / 256, 256>>>(x, wc, bias, sx, out);
}